// round 1
// baseline (speedup 1.0000x reference)
#include <cuda_runtime.h>
#include <cuda_bf16.h>

// BSplineNN: out[b,c] = sum_n coef[b,n,c] * B_{n,3}(x_b)
// B=4096, n=64, C=256, K=3, T=68.
// Key facts:
//  - basis is independent of c (x broadcast across channels)
//  - cubic B-spline local support: only indices {span-3..span} are nonzero
// One block per batch row: cooperative Cox-de Boor (exact reference
// recurrence incl. d==0 guards), then a <=4-term coalesced dot per channel.

#define NB 4096
#define NCOEF 64
#define NCH 256
#define NT 68   // knots per batch
#define DEG 3

__global__ __launch_bounds__(NCH, 8)
void bspline_kernel(const float* __restrict__ coef,   // [B, 64, 256]
                    const float* __restrict__ knots,  // [B, 68]
                    const float* __restrict__ inpce,  // [B, 1]
                    float* __restrict__ out)          // [B, 256]
{
    const int b   = blockIdx.x;
    const int tid = threadIdx.x;

    __shared__ float t[NT];
    __shared__ float b0[NT - 1];   // 67
    __shared__ float b1[NT - 2];   // 66
    __shared__ float b2[NT - 3];   // 65
    __shared__ float b3[NT - 4];   // 64
    __shared__ int   span;
    __shared__ float xs;

    if (tid < NT) t[tid] = knots[b * NT + tid];
    if (tid == 0) { xs = inpce[b]; span = -1; }
    __syncthreads();

    const float x = xs;

    // degree 0: indicator t[i] <= x < t[i+1]
    if (tid < NT - 1) {
        float v = (t[tid] <= x && x < t[tid + 1]) ? 1.0f : 0.0f;
        b0[tid] = v;
        if (v != 0.0f) span = tid;   // unique interval (knots sorted)
    }
    __syncthreads();

    // degree 1
    if (tid < NT - 2) {
        const int i = tid;
        float d1 = t[i + 1] - t[i];
        float d2 = t[i + 2] - t[i + 1];
        float w1 = (d1 == 0.0f) ? 0.0f : (x - t[i]) / d1;
        float w2 = (d2 == 0.0f) ? 0.0f : (t[i + 2] - x) / d2;
        b1[i] = w1 * b0[i] + w2 * b0[i + 1];
    }
    __syncthreads();

    // degree 2
    if (tid < NT - 3) {
        const int i = tid;
        float d1 = t[i + 2] - t[i];
        float d2 = t[i + 3] - t[i + 1];
        float w1 = (d1 == 0.0f) ? 0.0f : (x - t[i]) / d1;
        float w2 = (d2 == 0.0f) ? 0.0f : (t[i + 3] - x) / d2;
        b2[i] = w1 * b1[i] + w2 * b1[i + 1];
    }
    __syncthreads();

    // degree 3
    if (tid < NT - 4) {
        const int i = tid;
        float d1 = t[i + 3] - t[i];
        float d2 = t[i + 4] - t[i + 1];
        float w1 = (d1 == 0.0f) ? 0.0f : (x - t[i]) / d1;
        float w2 = (d2 == 0.0f) ? 0.0f : (t[i + 4] - x) / d2;
        b3[i] = w1 * b2[i] + w2 * b2[i + 1];
    }
    __syncthreads();

    // Sparse dot: only indices [span-3, span] clipped to [0, 63] are nonzero.
    float acc = 0.0f;
    const int j = span;
    if (j >= 0) {
        const int lo = max(j - DEG, 0);
        const int hi = min(j, NCOEF - 1);
        const float* crow = coef + ((long long)b * NCOEF) * NCH + tid;
        #pragma unroll 4
        for (int nn = lo; nn <= hi; nn++) {
            acc += crow[(long long)nn * NCH] * b3[nn];
        }
    }
    out[b * NCH + tid] = acc;
}

extern "C" void kernel_launch(void* const* d_in, const int* in_sizes, int n_in,
                              void* d_out, int out_size) {
    const float* coef  = (const float*)d_in[0];  // [4096, 64, 256]
    const float* knots = (const float*)d_in[1];  // [4096, 68]
    const float* inpce = (const float*)d_in[2];  // [4096, 1]
    float* out = (float*)d_out;                  // [4096, 256]

    bspline_kernel<<<NB, NCH>>>(coef, knots, inpce, out);
}

// round 2
// speedup vs baseline: 1.0200x; 1.0200x over previous
#include <cuda_runtime.h>
#include <cuda_bf16.h>

// BSplineNN: out[b,c] = sum_n coef[b,n,c] * B_{n,3}(x_b)
// B=4096, n=64, C=256, K=3, T=68.
//  - basis independent of c (x broadcast across channels)
//  - cubic B-spline local support: only n in {span-3..span} are nonzero,
//    AND the intermediate degree-1/2 values are only nonzero on
//    {span-1..span} / {span-2..span}. So warp 0 computes just 4+5+4 guarded
//    values (exact reference formulas incl. d==0 -> 0), everyone else only
//    does the 4-term coalesced dot. 2 barriers instead of 5.

#define NB    4096
#define NCOEF 64
#define NCH   256
#define NT    68

__global__ __launch_bounds__(NCH, 8)
void bspline_kernel(const float* __restrict__ coef,   // [B, 64, 256]
                    const float* __restrict__ knots,  // [B, 68]
                    const float* __restrict__ inpce,  // [B, 1]
                    float* __restrict__ out)          // [B, 256]
{
    const int b   = blockIdx.x;
    const int tid = threadIdx.x;

    __shared__ float t[NT];
    __shared__ float sw[4];
    __shared__ int   si[4];

    if (tid < NT) t[tid] = knots[b * NT + tid];
    __syncthreads();

    if (tid < 32) {
        const int lane = tid;
        const float x = inpce[b];   // broadcast LDG

        // vectorized span search: indicator t[i] <= x < t[i+1], i in [0,66]
        bool c1 = (t[lane] <= x) & (x < t[lane + 1]);                       // i = 0..31
        bool c2 = (t[lane + 32] <= x) & (x < t[lane + 33]);                 // i = 32..63
        bool c3 = (lane + 64 < NT - 1) && (t[lane + 64] <= x) && (x < t[lane + 65]); // i = 64..66
        unsigned m1 = __ballot_sync(0xffffffffu, c1);
        unsigned m2 = __ballot_sync(0xffffffffu, c2);
        unsigned m3 = __ballot_sync(0xffffffffu, c3);
        int j = m1 ? (__ffs(m1) - 1)
              : m2 ? (31 + __ffs(m2))
              : m3 ? (63 + __ffs(m3))
              : -1;

        float w[4] = {0.f, 0.f, 0.f, 0.f};
        if (j >= 0) {
            // degree-1: nonzero only at i in {j-1, j}; compute window i = j-2..j+1
            float B1[4];
            #pragma unroll
            for (int q = 0; q < 4; q++) {
                int i = j - 2 + q;
                float v = 0.f;
                if (i >= 0 && i <= NT - 3) {
                    if (i == j)     { float d = t[i + 1] - t[i];     if (d != 0.f) v += (x - t[i]) / d; }
                    if (i + 1 == j) { float d = t[i + 2] - t[i + 1]; if (d != 0.f) v += (t[i + 2] - x) / d; }
                }
                B1[q] = v;
            }
            // degree-2: window i = j-3..j+1
            float B2[5];
            #pragma unroll
            for (int q = 0; q < 5; q++) {
                int i = j - 3 + q;
                float v = 0.f;
                if (i >= 0 && i <= NT - 4) {
                    float d1 = t[i + 2] - t[i];
                    float d2 = t[i + 3] - t[i + 1];
                    float w1 = (d1 == 0.f) ? 0.f : (x - t[i]) / d1;
                    float w2 = (d2 == 0.f) ? 0.f : (t[i + 3] - x) / d2;
                    float u1 = (q >= 1) ? B1[q - 1] : 0.f;  // b1[i]
                    float u2 = (q <= 3) ? B1[q]     : 0.f;  // b1[i+1]
                    v = w1 * u1 + w2 * u2;
                }
                B2[q] = v;
            }
            // degree-3: n = j-3..j, valid basis indices 0..63
            #pragma unroll
            for (int q = 0; q < 4; q++) {
                int n = j - 3 + q;
                float v = 0.f;
                if (n >= 0 && n <= NT - 5) {
                    float d1 = t[n + 3] - t[n];
                    float d2 = t[n + 4] - t[n + 1];
                    float w1 = (d1 == 0.f) ? 0.f : (x - t[n]) / d1;
                    float w2 = (d2 == 0.f) ? 0.f : (t[n + 4] - x) / d2;
                    v = w1 * B2[q] + w2 * B2[q + 1];
                }
                w[q] = v;
            }
        }
        if (lane < 4) {
            sw[lane] = w[lane];
            int n = j - 3 + lane;
            si[lane] = min(max(n, 0), NCOEF - 1);   // clamped: loads always in-bounds,
                                                    // weight already 0 when out of support
        }
    }
    __syncthreads();

    // Unconditional 4-term dot, coalesced 1 KB row reads
    const float* crow = coef + ((long long)b * NCOEF) * NCH + tid;
    float acc;
    acc  = sw[0] * __ldg(crow + (long long)si[0] * NCH);
    acc += sw[1] * __ldg(crow + (long long)si[1] * NCH);
    acc += sw[2] * __ldg(crow + (long long)si[2] * NCH);
    acc += sw[3] * __ldg(crow + (long long)si[3] * NCH);
    out[b * NCH + tid] = acc;
}

extern "C" void kernel_launch(void* const* d_in, const int* in_sizes, int n_in,
                              void* d_out, int out_size) {
    const float* coef  = (const float*)d_in[0];  // [4096, 64, 256]
    const float* knots = (const float*)d_in[1];  // [4096, 68]
    const float* inpce = (const float*)d_in[2];  // [4096, 1]
    float* out = (float*)d_out;                  // [4096, 256]

    bspline_kernel<<<NB, NCH>>>(coef, knots, inpce, out);
}

// round 3
// speedup vs baseline: 1.4624x; 1.4337x over previous
#include <cuda_runtime.h>
#include <cuda_bf16.h>

// BSplineNN: out[b,c] = sum_n coef[b,n,c] * B_{n,3}(x_b)
// B=4096, n=64, C=256, K=3, T=68.
// One WARP per batch row. No shared memory, no __syncthreads.
//  - span found with 3 ballots
//  - all lanes redundantly compute the 4 locally-supported cubic weights
//    (redundant-across-lanes is free under SIMT); guarded __fdividef
//  - dot: each lane covers 8 channels via 2 float4 loads per row
//    -> 8 independent LDG.128 per lane (MLP=8), fully coalesced.

#define NB    4096
#define NCOEF 64
#define NCH   256
#define NT    68
#define WARPS_PER_BLOCK 8

__device__ __forceinline__ float gdiv(float a, float d) {
    return (d == 0.0f) ? 0.0f : __fdividef(a, d);
}

__global__ __launch_bounds__(WARPS_PER_BLOCK * 32)
void bspline_kernel(const float* __restrict__ coef,   // [B, 64, 256]
                    const float* __restrict__ knots,  // [B, 68]
                    const float* __restrict__ inpce,  // [B, 1]
                    float* __restrict__ out)          // [B, 256]
{
    const int b    = blockIdx.x * WARPS_PER_BLOCK + (threadIdx.x >> 5);
    const int lane = threadIdx.x & 31;

    const float* kt = knots + b * NT;
    const float  x  = __ldg(inpce + b);    // broadcast

    // ---- span search: indicator t[i] <= x < t[i+1], i in [0, 66] ----
    bool c1 = (__ldg(kt + lane)      <= x) & (x < __ldg(kt + lane + 1));
    bool c2 = (__ldg(kt + lane + 32) <= x) & (x < __ldg(kt + lane + 33));
    bool c3 = (lane < 3) && (__ldg(kt + lane + 64) <= x) && (x < __ldg(kt + lane + 65));
    unsigned m1 = __ballot_sync(0xffffffffu, c1);
    unsigned m2 = __ballot_sync(0xffffffffu, c2);
    unsigned m3 = __ballot_sync(0xffffffffu, c3);
    const int j = m1 ? (__ffs(m1) - 1)
                : m2 ? (31 + __ffs(m2))
                : m3 ? (63 + __ffs(m3))
                : -1;

    // ---- weights (all lanes compute identically; no divergence) ----
    float w0 = 0.f, w1 = 0.f, w2 = 0.f, w3 = 0.f;
    if (j >= 0) {
        // knot window t[j-3 .. j+4], clamped loads (values only used when
        // the same in-range guards as the reference recurrence pass)
        float tv[8];
        #pragma unroll
        for (int m = 0; m < 8; m++) {
            int i = j - 3 + m;
            tv[m] = __ldg(kt + min(max(i, 0), NT - 1));
        }
        // tv[i - (j-3)] == t[i]
        #define TV(i) tv[(i) - (j - 3)]

        // degree 1: nonzero only at i in {j-1, j}; window i = j-2..j+1
        float B1[4];
        #pragma unroll
        for (int q = 0; q < 4; q++) {
            int i = j - 2 + q;
            float v = 0.f;
            if (i >= 0 && i <= NT - 3) {
                if (i == j)     v += gdiv(x - TV(i),     TV(i + 1) - TV(i));
                if (i + 1 == j) v += gdiv(TV(i + 2) - x, TV(i + 2) - TV(i + 1));
            }
            B1[q] = v;
        }
        // degree 2: window i = j-3..j+1
        float B2[5];
        #pragma unroll
        for (int q = 0; q < 5; q++) {
            int i = j - 3 + q;
            float v = 0.f;
            if (i >= 0 && i <= NT - 4) {
                float a1 = gdiv(x - TV(i),     TV(i + 2) - TV(i));
                float a2 = gdiv(TV(i + 3) - x, TV(i + 3) - TV(i + 1));
                float u1 = (q >= 1) ? B1[q - 1] : 0.f;
                float u2 = (q <= 3) ? B1[q]     : 0.f;
                v = a1 * u1 + a2 * u2;
            }
            B2[q] = v;
        }
        // degree 3: n = j-3..j
        float wq[4];
        #pragma unroll
        for (int q = 0; q < 4; q++) {
            int n = j - 3 + q;
            float v = 0.f;
            if (n >= 0 && n <= NT - 5) {
                float a1 = gdiv(x - TV(n),     TV(n + 3) - TV(n));
                float a2 = gdiv(TV(n + 4) - x, TV(n + 4) - TV(n + 1));
                v = a1 * B2[q] + a2 * B2[q + 1];
            }
            wq[q] = v;
        }
        w0 = wq[0]; w1 = wq[1]; w2 = wq[2]; w3 = wq[3];
        #undef TV
    }

    // ---- 4-row dot, 8 channels per lane via float4 ----
    const int jc = (j < 0) ? 3 : j;                 // weights are 0 when j<0
    const int n0 = min(max(jc - 3, 0), NCOEF - 1);
    const int n1 = min(max(jc - 2, 0), NCOEF - 1);
    const int n2 = min(max(jc - 1, 0), NCOEF - 1);
    const int n3 = min(max(jc,     0), NCOEF - 1);

    const float4* cr = (const float4*)(coef + (long long)b * (NCOEF * NCH));
    const int c4 = lane * 2;                        // float4 index within a row (row = 64 float4)

    float4 r00 = __ldg(cr + n0 * 64 + c4);
    float4 r01 = __ldg(cr + n0 * 64 + c4 + 1);
    float4 r10 = __ldg(cr + n1 * 64 + c4);
    float4 r11 = __ldg(cr + n1 * 64 + c4 + 1);
    float4 r20 = __ldg(cr + n2 * 64 + c4);
    float4 r21 = __ldg(cr + n2 * 64 + c4 + 1);
    float4 r30 = __ldg(cr + n3 * 64 + c4);
    float4 r31 = __ldg(cr + n3 * 64 + c4 + 1);

    float4 a0, a1;
    a0.x = w0 * r00.x + w1 * r10.x + w2 * r20.x + w3 * r30.x;
    a0.y = w0 * r00.y + w1 * r10.y + w2 * r20.y + w3 * r30.y;
    a0.z = w0 * r00.z + w1 * r10.z + w2 * r20.z + w3 * r30.z;
    a0.w = w0 * r00.w + w1 * r10.w + w2 * r20.w + w3 * r30.w;
    a1.x = w0 * r01.x + w1 * r11.x + w2 * r21.x + w3 * r31.x;
    a1.y = w0 * r01.y + w1 * r11.y + w2 * r21.y + w3 * r31.y;
    a1.z = w0 * r01.z + w1 * r11.z + w2 * r21.z + w3 * r31.z;
    a1.w = w0 * r01.w + w1 * r11.w + w2 * r21.w + w3 * r31.w;

    float4* o = (float4*)(out + (long long)b * NCH);
    o[c4]     = a0;
    o[c4 + 1] = a1;
}

extern "C" void kernel_launch(void* const* d_in, const int* in_sizes, int n_in,
                              void* d_out, int out_size) {
    const float* coef  = (const float*)d_in[0];  // [4096, 64, 256]
    const float* knots = (const float*)d_in[1];  // [4096, 68]
    const float* inpce = (const float*)d_in[2];  // [4096, 1]
    float* out = (float*)d_out;                  // [4096, 256]

    bspline_kernel<<<NB / WARPS_PER_BLOCK, WARPS_PER_BLOCK * 32>>>(coef, knots, inpce, out);
}